// round 14
// baseline (speedup 1.0000x reference)
#include <cuda_runtime.h>
#include <cstdint>

// Scratch: pooled means [8 batches x 128 channels]
__device__ float g_pooled[1024];

// Per-batch completion counters on distinct 128B L2 lines.
struct __align__(128) PadCnt { unsigned int v; unsigned int pad[31]; };
__device__ PadCnt g_cnt_batch[8];

__device__ __forceinline__ float ldg_nc_f32(const float* p) {
    float v;
    asm volatile("ld.global.nc.L2::256B.f32 %0, [%1];" : "=f"(v) : "l"(p));
    return v;
}

__device__ __forceinline__ void prefetch_l2(const void* p) {
    asm volatile("prefetch.global.L2 [%0];" :: "l"(p));
}

// 1024 blocks x 256 threads; one 256x256 plane per block (blk = b*128 + c).
// Phase A: pooled[blk] = mean over even h, even w via scalar even-float loads
// with the L2::256B region hint (measured +12% DRAM throughput vs no hint),
// 16 independent loads in flight per thread (stride 4096 B), no reg cap
// (36 regs / 7 CTAs/SM measured optimal vs forced 32 regs / 8 CTAs).
// One block per batch (blk&127==100) re-prefetches the FC weights into L2 at
// the END of its Phase A — the streaming traffic evicts any start-of-kernel
// prefetch, and all batch tails fire in the final microsecond, so this makes
// tail weight loads L2-hits (~234 cyc) instead of cold DRAM (~600 cyc).
// Phase B: 128th-arriving block of each batch computes that batch's MLP slice.
__global__ __launch_bounds__(256) void fused_kernel(const float* __restrict__ bsrc,
                                                    const float* __restrict__ fc1_w,
                                                    const float* __restrict__ fc2_w,
                                                    float* __restrict__ out) {
    const int blk = blockIdx.x;                    // 0..1023
    const int tid = threadIdx.x;
    const int bb  = blk >> 7;                      // batch 0..7

    // ---------- Phase A ----------
    // Per-thread base: plane + even-col byte + starting even-row byte.
    const char* __restrict__ tb = (const char*)bsrc
        + ((size_t)blk << 18)                      // plane = 256 KB
        + ((tid & 127) << 3)                       // even-float col, 8 B stride
        + ((tid >> 7) << 11);                      // row 0 or row 2 (2048 B)

    float a0 = 0.f, a1 = 0.f, a2 = 0.f, a3 = 0.f;
    #pragma unroll
    for (int kk = 0; kk < 64; kk += 16) {
        float v[16];
        #pragma unroll
        for (int u = 0; u < 16; ++u)
            v[u] = ldg_nc_f32((const float*)(tb + (size_t)(kk + u) * 4096));
        #pragma unroll
        for (int u = 0; u < 16; u += 4) {
            a0 += v[u + 0];
            a1 += v[u + 1];
            a2 += v[u + 2];
            a3 += v[u + 3];
        }
    }
    float acc = (a0 + a1) + (a2 + a3);

    // Late L2 warm-up for this batch's tail: guaranteed to complete issuing
    // before this block's own counter arrival, hence before the batch-last
    // block can enter Phase B.
    if ((blk & 127) == 100) {
        prefetch_l2((const char*)fc1_w + tid * 64);   // 256*64 B = 16 KB
        prefetch_l2((const char*)fc2_w + tid * 64);   // 16 KB
    }

    #pragma unroll
    for (int off = 16; off > 0; off >>= 1)
        acc += __shfl_xor_sync(0xFFFFFFFFu, acc, off);

    __shared__ float warp_sums[8];
    __shared__ int is_batch_last;
    if ((tid & 31) == 0) warp_sums[tid >> 5] = acc;
    if (tid == 0) is_batch_last = 0;
    __syncthreads();

    if (tid == 0) {
        float s = warp_sums[0];
        #pragma unroll
        for (int w = 1; w < 8; ++w) s += warp_sums[w];
        g_pooled[blk] = s * (1.0f / 65536.0f);
        __threadfence();                           // publish before counting

        unsigned int old = atomicAdd(&g_cnt_batch[bb].v, 1u);
        if (old == 127u) {
            g_cnt_batch[bb].v = 0u;                // reset for next graph replay
            is_batch_last = 1;
        }
    }
    __syncthreads();
    if (!is_batch_last) return;

    // ---------- Phase B: this batch's slice of the MLP (rare path) ----------
    __shared__ __align__(16) float sp[128];        // pooled[bb][0..127]
    __shared__ __align__(16) float sh[32];         // hidden[bb][0..31]

    if (tid < 128) sp[tid] = __ldcg(&g_pooled[(bb << 7) + tid]);
    __syncthreads();

    // hidden[j] = relu( sum_c sp[c] * fc1_w[j][c] ), 8 threads per unit j.
    {
        const int j = tid >> 3;                    // hidden unit 0..31
        const int k = tid & 7;                     // sub-lane, 16 channels each
        const float4* __restrict__ w4 = reinterpret_cast<const float4*>(fc1_w) + j * 32 + k * 4;
        const float4* __restrict__ p4 = reinterpret_cast<const float4*>(sp) + k * 4;
        float s = 0.0f;
        #pragma unroll
        for (int q = 0; q < 4; ++q) {
            float4 w = w4[q];
            float4 p = p4[q];
            s = fmaf(w.x, p.x, s);
            s = fmaf(w.y, p.y, s);
            s = fmaf(w.z, p.z, s);
            s = fmaf(w.w, p.w, s);
        }
        s += __shfl_xor_sync(0xFFFFFFFFu, s, 4);
        s += __shfl_xor_sync(0xFFFFFFFFu, s, 2);
        s += __shfl_xor_sync(0xFFFFFFFFu, s, 1);
        if (k == 0) sh[j] = fmaxf(s, 0.0f);
    }
    __syncthreads();

    // out[bb*128 + c] = sum_j sh[j] * fc2_w[c][j]; threads 0..127, one output each.
    if (tid < 128) {
        const float4* __restrict__ w4 = reinterpret_cast<const float4*>(fc2_w) + tid * 8;
        const float4* __restrict__ h4 = reinterpret_cast<const float4*>(sh);
        float s = 0.0f;
        #pragma unroll
        for (int q = 0; q < 8; ++q) {
            float4 w = w4[q];
            float4 h = h4[q];
            s = fmaf(w.x, h.x, s);
            s = fmaf(w.y, h.y, s);
            s = fmaf(w.z, h.z, s);
            s = fmaf(w.w, h.w, s);
        }
        out[(bb << 7) + tid] = s;
    }
}

extern "C" void kernel_launch(void* const* d_in, const int* in_sizes, int n_in,
                              void* d_out, int out_size) {
    // metadata order: a, b, attn_w, attn_b, fc1_w, fc2_w
    const float* bsrc  = (const float*)d_in[1];
    const float* fc1_w = (const float*)d_in[4];
    const float* fc2_w = (const float*)d_in[5];
    float* out = (float*)d_out;

    fused_kernel<<<1024, 256>>>(bsrc, fc1_w, fc2_w, out);
}

// round 15
// speedup vs baseline: 1.0202x; 1.0202x over previous
#include <cuda_runtime.h>
#include <cstdint>

// Scratch: pooled means [8 batches x 128 channels]
__device__ float g_pooled[1024];

// Per-batch completion counters on distinct 128B L2 lines.
struct __align__(128) PadCnt { unsigned int v; unsigned int pad[31]; };
__device__ PadCnt g_cnt_batch[8];

__device__ __forceinline__ float ldg_nc_f32(const float* p) {
    float v;
    asm volatile("ld.global.nc.L2::256B.f32 %0, [%1];" : "=f"(v) : "l"(p));
    return v;
}

__device__ __forceinline__ void prefetch_l2(const void* p) {
    asm volatile("prefetch.global.L2 [%0];" :: "l"(p));
}

// CONVERGED CONFIGURATION (measured optimum over 14 rounds):
// 1024 blocks x 256 threads; one 256x256 plane per block (blk = b*128 + c).
// Phase A: pooled[blk] = mean over even h, even w via scalar even-float loads
//   with the L2::256B region hint (+11% DRAM vs no hint), 16 independent
//   loads in flight per thread (depth 8 was -4%), natural 36 regs / 7 CTAs/SM
//   (forced 32 regs / 8 CTAs was -4%; cp.async.bulk pipeline was -24%;
//   any branch inserted in the streaming region was -9%).
// Phase B: 128th-arriving block of each batch computes that batch's MLP slice
//   (per-batch tails overlap 7 of 8 tails with ongoing Phase-A traffic).
__global__ __launch_bounds__(256) void fused_kernel(const float* __restrict__ bsrc,
                                                    const float* __restrict__ fc1_w,
                                                    const float* __restrict__ fc2_w,
                                                    float* __restrict__ out) {
    const int blk = blockIdx.x;                    // 0..1023
    const int tid = threadIdx.x;
    const int bb  = blk >> 7;                      // batch 0..7

    // Warm L2 with FC weights (2 x 16 KB); outside the hot streaming region.
    if (blk == 0) {
        prefetch_l2((const char*)fc1_w + tid * 64);
        prefetch_l2((const char*)fc2_w + tid * 64);
    }

    // ---------- Phase A ----------
    // Per-thread base: plane + even-col byte + starting even-row byte.
    const char* __restrict__ tb = (const char*)bsrc
        + ((size_t)blk << 18)                      // plane = 256 KB
        + ((tid & 127) << 3)                       // even-float col, 8 B stride
        + ((tid >> 7) << 11);                      // row 0 or row 2 (2048 B)

    float a0 = 0.f, a1 = 0.f, a2 = 0.f, a3 = 0.f;
    #pragma unroll
    for (int kk = 0; kk < 64; kk += 16) {
        float v[16];
        #pragma unroll
        for (int u = 0; u < 16; ++u)
            v[u] = ldg_nc_f32((const float*)(tb + (size_t)(kk + u) * 4096));
        #pragma unroll
        for (int u = 0; u < 16; u += 4) {
            a0 += v[u + 0];
            a1 += v[u + 1];
            a2 += v[u + 2];
            a3 += v[u + 3];
        }
    }
    float acc = (a0 + a1) + (a2 + a3);

    #pragma unroll
    for (int off = 16; off > 0; off >>= 1)
        acc += __shfl_xor_sync(0xFFFFFFFFu, acc, off);

    __shared__ float warp_sums[8];
    __shared__ int is_batch_last;
    if ((tid & 31) == 0) warp_sums[tid >> 5] = acc;
    if (tid == 0) is_batch_last = 0;
    __syncthreads();

    if (tid == 0) {
        float s = warp_sums[0];
        #pragma unroll
        for (int w = 1; w < 8; ++w) s += warp_sums[w];
        g_pooled[blk] = s * (1.0f / 65536.0f);
        __threadfence();                           // publish before counting

        unsigned int old = atomicAdd(&g_cnt_batch[bb].v, 1u);
        if (old == 127u) {
            g_cnt_batch[bb].v = 0u;                // reset for next graph replay
            is_batch_last = 1;
        }
    }
    __syncthreads();
    if (!is_batch_last) return;

    // ---------- Phase B: this batch's slice of the MLP (rare path) ----------
    __shared__ __align__(16) float sp[128];        // pooled[bb][0..127]
    __shared__ __align__(16) float sh[32];         // hidden[bb][0..31]

    if (tid < 128) sp[tid] = __ldcg(&g_pooled[(bb << 7) + tid]);
    __syncthreads();

    // hidden[j] = relu( sum_c sp[c] * fc1_w[j][c] ), 8 threads per unit j.
    {
        const int j = tid >> 3;                    // hidden unit 0..31
        const int k = tid & 7;                     // sub-lane, 16 channels each
        const float4* __restrict__ w4 = reinterpret_cast<const float4*>(fc1_w) + j * 32 + k * 4;
        const float4* __restrict__ p4 = reinterpret_cast<const float4*>(sp) + k * 4;
        float s = 0.0f;
        #pragma unroll
        for (int q = 0; q < 4; ++q) {
            float4 w = w4[q];
            float4 p = p4[q];
            s = fmaf(w.x, p.x, s);
            s = fmaf(w.y, p.y, s);
            s = fmaf(w.z, p.z, s);
            s = fmaf(w.w, p.w, s);
        }
        s += __shfl_xor_sync(0xFFFFFFFFu, s, 4);
        s += __shfl_xor_sync(0xFFFFFFFFu, s, 2);
        s += __shfl_xor_sync(0xFFFFFFFFu, s, 1);
        if (k == 0) sh[j] = fmaxf(s, 0.0f);
    }
    __syncthreads();

    // out[bb*128 + c] = sum_j sh[j] * fc2_w[c][j]; threads 0..127, one output each.
    if (tid < 128) {
        const float4* __restrict__ w4 = reinterpret_cast<const float4*>(fc2_w) + tid * 8;
        const float4* __restrict__ h4 = reinterpret_cast<const float4*>(sh);
        float s = 0.0f;
        #pragma unroll
        for (int q = 0; q < 8; ++q) {
            float4 w = w4[q];
            float4 h = h4[q];
            s = fmaf(w.x, h.x, s);
            s = fmaf(w.y, h.y, s);
            s = fmaf(w.z, h.z, s);
            s = fmaf(w.w, h.w, s);
        }
        out[(bb << 7) + tid] = s;
    }
}

extern "C" void kernel_launch(void* const* d_in, const int* in_sizes, int n_in,
                              void* d_out, int out_size) {
    // metadata order: a, b, attn_w, attn_b, fc1_w, fc2_w
    const float* bsrc  = (const float*)d_in[1];
    const float* fc1_w = (const float*)d_in[4];
    const float* fc2_w = (const float*)d_in[5];
    float* out = (float*)d_out;

    fused_kernel<<<1024, 256>>>(bsrc, fc1_w, fc2_w, out);
}

// round 16
// speedup vs baseline: 1.0708x; 1.0496x over previous
#include <cuda_runtime.h>
#include <cstdint>

// Per-half partial sums: [plane 0..1023][half 0..1] -> 2048 entries
__device__ float g_part[2048];

// Per-batch completion counters on distinct 128B L2 lines.
struct __align__(128) PadCnt { unsigned int v; unsigned int pad[31]; };
__device__ PadCnt g_cnt_batch[8];

__device__ __forceinline__ float ldg_nc_f32(const float* p) {
    float v;
    asm volatile("ld.global.nc.L2::256B.f32 %0, [%1];" : "=f"(v) : "l"(p));
    return v;
}

__device__ __forceinline__ void prefetch_l2(const void* p) {
    asm volatile("prefetch.global.L2 [%0];" :: "l"(p));
}

// 2048 blocks x 256 threads; one HALF-plane per block (finer drain granularity:
// block lifetime ~1.9us vs ~3.8us at grid 1024). Stream structure identical to
// the converged optimum: scalar even-float loads with L2::256B hint, 16-deep
// independent batches (2 of them), natural regs.
// blk = plane*2 + half;  plane = b*128 + c.
// Phase B: 256th-arriving block of each batch computes that batch's MLP slice.
__global__ __launch_bounds__(256) void fused_kernel(const float* __restrict__ bsrc,
                                                    const float* __restrict__ fc1_w,
                                                    const float* __restrict__ fc2_w,
                                                    float* __restrict__ out) {
    const int blk = blockIdx.x;                    // 0..2047
    const int tid = threadIdx.x;
    const int bb  = blk >> 8;                      // batch 0..7 (256 blocks/batch)

    // Warm L2 with FC weights (2 x 16 KB); outside the hot streaming region.
    if (blk == 0) {
        prefetch_l2((const char*)fc1_w + tid * 64);
        prefetch_l2((const char*)fc2_w + tid * 64);
    }

    // ---------- Phase A ----------
    // plane = blk>>1 (256 KB each), half = blk&1 (rows [half*128, half*128+128)).
    // Thread base: even-col byte (8 B stride) + starting even-row (0 or 2).
    const char* __restrict__ tb = (const char*)bsrc
        + ((size_t)(blk >> 1) << 18)               // plane = 256 KB
        + ((size_t)(blk & 1) << 17)                // half  = 128 KB
        + ((tid & 127) << 3)                       // even-float col
        + ((tid >> 7) << 11);                      // row 0 or row 2

    float a0 = 0.f, a1 = 0.f, a2 = 0.f, a3 = 0.f;
    #pragma unroll
    for (int kk = 0; kk < 32; kk += 16) {
        float v[16];
        #pragma unroll
        for (int u = 0; u < 16; ++u)
            v[u] = ldg_nc_f32((const float*)(tb + (size_t)(kk + u) * 4096));
        #pragma unroll
        for (int u = 0; u < 16; u += 4) {
            a0 += v[u + 0];
            a1 += v[u + 1];
            a2 += v[u + 2];
            a3 += v[u + 3];
        }
    }
    float acc = (a0 + a1) + (a2 + a3);

    #pragma unroll
    for (int off = 16; off > 0; off >>= 1)
        acc += __shfl_xor_sync(0xFFFFFFFFu, acc, off);

    __shared__ float warp_sums[8];
    __shared__ int is_batch_last;
    if ((tid & 31) == 0) warp_sums[tid >> 5] = acc;
    if (tid == 0) is_batch_last = 0;
    __syncthreads();

    if (tid == 0) {
        float s = warp_sums[0];
        #pragma unroll
        for (int w = 1; w < 8; ++w) s += warp_sums[w];
        g_part[blk] = s;                           // raw partial sum (half-plane)
        __threadfence();                           // publish before counting

        unsigned int old = atomicAdd(&g_cnt_batch[bb].v, 1u);
        if (old == 255u) {
            g_cnt_batch[bb].v = 0u;                // reset for next graph replay
            is_batch_last = 1;
        }
    }
    __syncthreads();
    if (!is_batch_last) return;

    // ---------- Phase B: this batch's slice of the MLP (rare path) ----------
    __shared__ __align__(16) float sp[128];        // pooled[bb][0..127]
    __shared__ __align__(16) float sh[32];         // hidden[bb][0..31]

    if (tid < 128) {
        const int e = (bb << 8) + (tid << 1);      // entries blk = (bb*128+c)*2
        const float h0 = __ldcg(&g_part[e]);
        const float h1 = __ldcg(&g_part[e + 1]);
        sp[tid] = (h0 + h1) * (1.0f / 65536.0f);
    }
    __syncthreads();

    // hidden[j] = relu( sum_c sp[c] * fc1_w[j][c] ), 8 threads per unit j.
    {
        const int j = tid >> 3;                    // hidden unit 0..31
        const int k = tid & 7;                     // sub-lane, 16 channels each
        const float4* __restrict__ w4 = reinterpret_cast<const float4*>(fc1_w) + j * 32 + k * 4;
        const float4* __restrict__ p4 = reinterpret_cast<const float4*>(sp) + k * 4;
        float s = 0.0f;
        #pragma unroll
        for (int q = 0; q < 4; ++q) {
            float4 w = w4[q];
            float4 p = p4[q];
            s = fmaf(w.x, p.x, s);
            s = fmaf(w.y, p.y, s);
            s = fmaf(w.z, p.z, s);
            s = fmaf(w.w, p.w, s);
        }
        s += __shfl_xor_sync(0xFFFFFFFFu, s, 4);
        s += __shfl_xor_sync(0xFFFFFFFFu, s, 2);
        s += __shfl_xor_sync(0xFFFFFFFFu, s, 1);
        if (k == 0) sh[j] = fmaxf(s, 0.0f);
    }
    __syncthreads();

    // out[bb*128 + c] = sum_j sh[j] * fc2_w[c][j]; threads 0..127, one output each.
    if (tid < 128) {
        const float4* __restrict__ w4 = reinterpret_cast<const float4*>(fc2_w) + tid * 8;
        const float4* __restrict__ h4 = reinterpret_cast<const float4*>(sh);
        float s = 0.0f;
        #pragma unroll
        for (int q = 0; q < 8; ++q) {
            float4 w = w4[q];
            float4 h = h4[q];
            s = fmaf(w.x, h.x, s);
            s = fmaf(w.y, h.y, s);
            s = fmaf(w.z, h.z, s);
            s = fmaf(w.w, h.w, s);
        }
        out[(bb << 7) + tid] = s;
    }
}

extern "C" void kernel_launch(void* const* d_in, const int* in_sizes, int n_in,
                              void* d_out, int out_size) {
    // metadata order: a, b, attn_w, attn_b, fc1_w, fc2_w
    const float* bsrc  = (const float*)d_in[1];
    const float* fc1_w = (const float*)d_in[4];
    const float* fc2_w = (const float*)d_in[5];
    float* out = (float*)d_out;

    fused_kernel<<<2048, 256>>>(bsrc, fc1_w, fc2_w, out);
}